// round 10
// baseline (speedup 1.0000x reference)
#include <cuda_runtime.h>

#define N_PTS   4096
#define PAIRS   8
#define TPB     128
#define J_TILE  512
#define JP_TILE (J_TILE / 2)              // 256 j-pairs per tile
#define I_TILE  256                       // 2 i-points per thread * 128 threads
#define J_SPLITS (N_PTS / J_TILE)         // 8
#define I_GROUPS (N_PTS / I_TILE)         // 16
#define BLOCKS_PER_PAIR (J_SPLITS * I_GROUPS)   // 128
#define T_DIM   4
#define INV_SCALE (1.0f / (T_DIM * N_PTS))
#define FINF    3.0e38f

// Partial (na2 + min over j-chunk) per (pair, i, jsplit): [8][4096][8] floats = 1 MB
__device__ float4       g_part4[PAIRS * N_PTS * 2];
__device__ unsigned int g_done[PAIRS];     // zero-init; returns to 0 every run
__device__ unsigned int g_done2;           // zero-init; returns to 0 every run
__device__ float        g_pairsum[PAIRS];

typedef unsigned long long u64;

__device__ __forceinline__ u64 pk(float lo, float hi) {
    return ((u64)__float_as_uint(hi) << 32) | (u64)__float_as_uint(lo);
}
__device__ __forceinline__ float flo(u64 v) { return __uint_as_float((unsigned)v); }
__device__ __forceinline__ float fhi(u64 v) { return __uint_as_float((unsigned)(v >> 32)); }

__device__ __forceinline__ u64 fma2(u64 a, u64 b, u64 c) {
    u64 d;
    asm("fma.rn.f32x2 %0, %1, %2, %3;" : "=l"(d) : "l"(a), "l"(b), "l"(c));
    return d;
}

__global__ __launch_bounds__(TPB)
void hd_fused(const float* __restrict__ d1,
              const float* __restrict__ d2,
              float* __restrict__ out) {
    // Per j-pair: sA = (bx0,bx1 | by0,by1), sB = (bz0,bz1 | w0,w1)  -> 8 KB
    __shared__ ulonglong2 sA[JP_TILE];
    __shared__ ulonglong2 sB[JP_TILE];
    __shared__ float red[TPB / 32];
    __shared__ int  s_flag;

    const int jsplit = blockIdx.x;
    const int ibase  = blockIdx.y * I_TILE;
    const int pair   = blockIdx.z;
    const int jbase  = jsplit * J_TILE;

    // ---- Stage: each thread packs two j-pairs (6 contiguous floats each) ----
    {
        const float2* f2 = (const float2*)(d2 + ((size_t)pair * N_PTS + jbase) * 3);
        #pragma unroll
        for (int jp = threadIdx.x; jp < JP_TILE; jp += TPB) {
            float2 a = f2[3 * jp + 0];               // bx0, by0
            float2 b = f2[3 * jp + 1];               // bz0, bx1
            float2 c = f2[3 * jp + 2];               // by1, bz1
            float w0 = fmaf(a.x, a.x, fmaf(a.y, a.y, b.x * b.x));
            float w1 = fmaf(b.y, b.y, fmaf(c.x, c.x, c.y * c.y));
            sA[jp] = make_ulonglong2(pk(a.x, b.y), pk(a.y, c.x));
            sB[jp] = make_ulonglong2(pk(b.x, c.y), pk(w0, w1));
        }
    }
    __syncthreads();

    // ---- Mainloop: two set-1 points per thread, packed f32x2 math ----
    const int i0 = ibase + threadIdx.x;
    const int i1 = i0 + TPB;
    const float* pa0 = d1 + ((size_t)pair * N_PTS + i0) * 3;
    const float* pa1 = d1 + ((size_t)pair * N_PTS + i1) * 3;
    const float a0x = pa0[0], a0y = pa0[1], a0z = pa0[2];
    const float a1x = pa1[0], a1y = pa1[1], a1z = pa1[2];
    const float na0 = fmaf(a0x, a0x, fmaf(a0y, a0y, a0z * a0z));
    const float na1 = fmaf(a1x, a1x, fmaf(a1y, a1y, a1z * a1z));
    const u64 ax0p = pk(-2.0f * a0x, -2.0f * a0x);
    const u64 ay0p = pk(-2.0f * a0y, -2.0f * a0y);
    const u64 az0p = pk(-2.0f * a0z, -2.0f * a0z);
    const u64 ax1p = pk(-2.0f * a1x, -2.0f * a1x);
    const u64 ay1p = pk(-2.0f * a1y, -2.0f * a1y);
    const u64 az1p = pk(-2.0f * a1z, -2.0f * a1z);

    float m00 = FINF, m01 = FINF;    // point i0: lo/hi chains
    float m10 = FINF, m11 = FINF;    // point i1

    #pragma unroll 4
    for (int jp = 0; jp < JP_TILE; ++jp) {
        ulonglong2 qA = sA[jp];      // (bx pair, by pair)
        ulonglong2 qB = sB[jp];      // (bz pair, w pair)

        u64 t0 = fma2(ax0p, qA.x, qB.y);
        u64 t1 = fma2(ax1p, qA.x, qB.y);
        t0 = fma2(ay0p, qA.y, t0);
        t1 = fma2(ay1p, qA.y, t1);
        t0 = fma2(az0p, qB.x, t0);
        t1 = fma2(az1p, qB.x, t1);

        m00 = fminf(m00, flo(t0));
        m01 = fminf(m01, fhi(t0));
        m10 = fminf(m10, flo(t1));
        m11 = fminf(m11, fhi(t1));
    }

    float* part = (float*)g_part4;
    part[(((size_t)pair * N_PTS + i0) << 3) + jsplit] = na0 + fminf(m00, m01);
    part[(((size_t)pair * N_PTS + i1) << 3) + jsplit] = na1 + fminf(m10, m11);

    // ---- Release our partials, bump the pair counter; last block finishes ----
    __threadfence();
    __syncthreads();
    if (threadIdx.x == 0) {
        unsigned int old = atomicAdd(&g_done[pair], 1u);
        s_flag = (old == BLOCKS_PER_PAIR - 1);
    }
    __syncthreads();
    if (!s_flag) return;

    // ---- Pair finisher: min over 8 j-split partials, sqrt, sum ----
    __threadfence();  // acquire all writers' partials
    const float4* base = g_part4 + (size_t)pair * N_PTS * 2;
    float acc = 0.0f;
    for (int k = threadIdx.x; k < N_PTS; k += TPB) {
        float4 p0 = base[2 * k + 0];
        float4 p1 = base[2 * k + 1];
        float m = fminf(fminf(fminf(p0.x, p0.y), fminf(p0.z, p0.w)),
                        fminf(fminf(p1.x, p1.y), fminf(p1.z, p1.w)));
        acc += sqrtf(fmaxf(m, 0.0f));
    }

    #pragma unroll
    for (int off = 16; off > 0; off >>= 1)
        acc += __shfl_xor_sync(0xFFFFFFFFu, acc, off);
    const int lane = threadIdx.x & 31;
    const int wid  = threadIdx.x >> 5;
    if (lane == 0) red[wid] = acc;
    __syncthreads();

    if (threadIdx.x == 0) {
        float total = red[0] + red[1] + red[2] + red[3];
        g_pairsum[pair] = total;
        g_done[pair] = 0;                 // reset for next graph replay
        __threadfence();                  // release pairsum (and reset)
        unsigned int old2 = atomicAdd(&g_done2, 1u);
        if (old2 == PAIRS - 1) {
            // ---- Global finisher: fixed-order sums -> deterministic output ----
            __threadfence();              // acquire all pairsums
            float s0 = ((g_pairsum[0] + g_pairsum[1]) +
                        (g_pairsum[2] + g_pairsum[3]));
            float s1 = ((g_pairsum[4] + g_pairsum[5]) +
                        (g_pairsum[6] + g_pairsum[7]));
            out[0] = s0 * INV_SCALE;
            out[1] = s1 * INV_SCALE;
            g_done2 = 0;                  // reset for next graph replay
        }
    }
}

extern "C" void kernel_launch(void* const* d_in, const int* in_sizes, int n_in,
                              void* d_out, int out_size) {
    const float* d1 = (const float*)d_in[0];
    const float* d2 = (const float*)d_in[1];
    float* out = (float*)d_out;

    dim3 grid(J_SPLITS, I_GROUPS, PAIRS);
    hd_fused<<<grid, TPB>>>(d1, d2, out);
}

// round 11
// speedup vs baseline: 1.2829x; 1.2829x over previous
#include <cuda_runtime.h>

#define N_PTS   4096
#define PAIRS   8
#define TPB     256
#define J_TILE  256
#define JP_TILE (J_TILE / 2)              // 128 j-pairs per tile
#define I_TILE  1024                      // 4 i-points per thread * 256 threads
#define J_SPLITS (N_PTS / J_TILE)         // 16
#define I_GROUPS (N_PTS / I_TILE)         // 4
#define T_DIM   4
#define INV_SCALE (1.0f / (T_DIM * N_PTS))
#define FINF    3.0e38f

// Partial (na2 + min over j-chunk) per (pair, i, jsplit): [8][4096][16] floats = 2 MB
__device__ float4 g_part4[PAIRS * N_PTS * 4];

typedef unsigned long long u64;

__device__ __forceinline__ u64 pk(float lo, float hi) {
    return ((u64)__float_as_uint(hi) << 32) | (u64)__float_as_uint(lo);
}
__device__ __forceinline__ float flo(u64 v) { return __uint_as_float((unsigned)v); }
__device__ __forceinline__ float fhi(u64 v) { return __uint_as_float((unsigned)(v >> 32)); }

__device__ __forceinline__ u64 fma2(u64 a, u64 b, u64 c) {
    u64 d;
    asm("fma.rn.f32x2 %0, %1, %2, %3;" : "=l"(d) : "l"(a), "l"(b), "l"(c));
    return d;
}

__global__ __launch_bounds__(TPB)
void hd_nn_kernel(const float* __restrict__ d1,
                  const float* __restrict__ d2,
                  float* __restrict__ out) {
    // Per j-pair: sA = (bx0,bx1 | by0,by1), sB = (bz0,bz1 | w0,w1)  -> 4 KB
    __shared__ ulonglong2 sA[JP_TILE];
    __shared__ ulonglong2 sB[JP_TILE];

    const int jsplit = blockIdx.x;
    const int ibase  = blockIdx.y * I_TILE;
    const int pair   = blockIdx.z;
    const int jbase  = jsplit * J_TILE;

    // Zero the output accumulators (visible to hd_final via kernel boundary)
    if (jsplit == 0 && blockIdx.y == 0 && pair == 0 && threadIdx.x < 2)
        out[threadIdx.x] = 0.0f;

    // Stage: threads 0..127 each pack one j-pair (6 contiguous floats)
    if (threadIdx.x < JP_TILE) {
        const float2* f2 = (const float2*)(d2 + ((size_t)pair * N_PTS + jbase) * 3);
        const int jp = threadIdx.x;
        float2 a = f2[3 * jp + 0];                   // bx0, by0
        float2 b = f2[3 * jp + 1];                   // bz0, bx1
        float2 c = f2[3 * jp + 2];                   // by1, bz1
        float w0 = fmaf(a.x, a.x, fmaf(a.y, a.y, b.x * b.x));
        float w1 = fmaf(b.y, b.y, fmaf(c.x, c.x, c.y * c.y));
        sA[jp] = make_ulonglong2(pk(a.x, b.y), pk(a.y, c.x));
        sB[jp] = make_ulonglong2(pk(b.x, c.y), pk(w0, w1));
    }
    __syncthreads();

    // Four set-1 points per thread; coefs packed (broadcast to both halves)
    u64 axp[4], ayp[4], azp[4];
    float na[4];
    #pragma unroll
    for (int k = 0; k < 4; ++k) {
        const int i = ibase + threadIdx.x + k * TPB;
        const float* pa = d1 + ((size_t)pair * N_PTS + i) * 3;
        float ax = pa[0], ay = pa[1], az = pa[2];
        na[k] = fmaf(ax, ax, fmaf(ay, ay, az * az));
        axp[k] = pk(-2.0f * ax, -2.0f * ax);
        ayp[k] = pk(-2.0f * ay, -2.0f * ay);
        azp[k] = pk(-2.0f * az, -2.0f * az);
    }

    float mlo[4], mhi[4];
    #pragma unroll
    for (int k = 0; k < 4; ++k) { mlo[k] = FINF; mhi[k] = FINF; }

    #pragma unroll 2
    for (int jp = 0; jp < JP_TILE; ++jp) {
        ulonglong2 qA = sA[jp];      // (bx pair, by pair)
        ulonglong2 qB = sB[jp];      // (bz pair, w pair)

        #pragma unroll
        for (int k = 0; k < 4; ++k) {
            u64 t = fma2(axp[k], qA.x, qB.y);
            t = fma2(ayp[k], qA.y, t);
            t = fma2(azp[k], qB.x, t);
            mlo[k] = fminf(mlo[k], flo(t));
            mhi[k] = fminf(mhi[k], fhi(t));
        }
    }

    float* part = (float*)g_part4;
    #pragma unroll
    for (int k = 0; k < 4; ++k) {
        const int i = ibase + threadIdx.x + k * TPB;
        part[(((size_t)pair * N_PTS + i) << 4) + jsplit] =
            na[k] + fminf(mlo[k], mhi[k]);
    }
}

// 128 blocks: each handles 256 i-points of one pair (one element per thread),
// then one atomicAdd per block into out[b].
#define FBLOCKS_PER_PAIR 16
__global__ __launch_bounds__(TPB)
void hd_final(float* __restrict__ out) {
    __shared__ float red[TPB / 32];
    const int pair  = blockIdx.x / FBLOCKS_PER_PAIR;
    const int chunk = blockIdx.x % FBLOCKS_PER_PAIR;
    const size_t e  = (size_t)pair * N_PTS + chunk * TPB + threadIdx.x;

    float4 p0 = g_part4[4 * e + 0];
    float4 p1 = g_part4[4 * e + 1];
    float4 p2 = g_part4[4 * e + 2];
    float4 p3 = g_part4[4 * e + 3];
    float m01 = fminf(fminf(fminf(p0.x, p0.y), fminf(p0.z, p0.w)),
                      fminf(fminf(p1.x, p1.y), fminf(p1.z, p1.w)));
    float m23 = fminf(fminf(fminf(p2.x, p2.y), fminf(p2.z, p2.w)),
                      fminf(fminf(p3.x, p3.y), fminf(p3.z, p3.w)));
    float acc = sqrtf(fmaxf(fminf(m01, m23), 0.0f));

    #pragma unroll
    for (int off = 16; off > 0; off >>= 1)
        acc += __shfl_xor_sync(0xFFFFFFFFu, acc, off);

    const int lane = threadIdx.x & 31;
    const int wid  = threadIdx.x >> 5;
    if (lane == 0) red[wid] = acc;
    __syncthreads();

    if (wid == 0) {
        float v = (lane < TPB / 32) ? red[lane] : 0.0f;
        #pragma unroll
        for (int off = 4; off > 0; off >>= 1)
            v += __shfl_xor_sync(0xFFFFFFFFu, v, off);
        if (lane == 0)
            atomicAdd(&out[pair >> 2], v * INV_SCALE);
    }
}

extern "C" void kernel_launch(void* const* d_in, const int* in_sizes, int n_in,
                              void* d_out, int out_size) {
    const float* d1 = (const float*)d_in[0];
    const float* d2 = (const float*)d_in[1];
    float* out = (float*)d_out;

    dim3 grid(J_SPLITS, I_GROUPS, PAIRS);
    hd_nn_kernel<<<grid, TPB>>>(d1, d2, out);
    hd_final<<<PAIRS * FBLOCKS_PER_PAIR, TPB>>>(out);
}